// round 7
// baseline (speedup 1.0000x reference)
#include <cuda_runtime.h>
#include <cstdint>
#include <cstddef>

// Problem dims
#define B_   8
#define T_   4096
#define D_   1024
#define BT_  (B_ * T_)          // 32768 rows
#define NBIG 3072               // W1(1024) + Wc1(1024) + Wc2(1024)

// GEMM tiling: 128x256 CTA tile, 16 warps of 64x32, K-step 16, 4-stage pipeline
#define BM   128
#define BN   256
#define BK   16
#define KT   (D_ / BK)          // 64 k-iterations
#define NS   4
#define NTH  512
#define SKF  24                 // smem row stride in floats (96B, conflict-free float2 frags)
#define STGF ((BM + BN) * SKF)  // floats per stage = 9216
#define SMEM_BYTES (NS * STGF * 4)   // 147456

// scan tiling
#define TT    64
#define NTILE (T_ / TT)

// ---------------- scratch ----------------
__device__ __align__(256) float g_s[BT_];
__device__ __align__(256) float g_e[BT_];
__device__ __align__(256) float g_pex[B_ * NTILE * D_];
__device__ __align__(256) float g_pe[B_ * NTILE];
__device__ __align__(256) float g_y1[(size_t)BT_ * D_];          // x @ Wc1^T
__device__ __align__(256) float g_y2[(size_t)BT_ * D_];          // x @ Wc2^T
__device__ __align__(256) float g_xr[(size_t)BT_ * D_];          // x, tf32-rounded, k-permuted
__device__ __align__(256) float g_wr[(size_t)NBIG * D_];         // [W1;Wc1;Wc2], rounded, permuted

// ---------------- PTX helpers ----------------
__device__ __forceinline__ void cp16(void* dst_smem, const void* src_gmem) {
    uint32_t s = (uint32_t)__cvta_generic_to_shared(dst_smem);
    asm volatile("cp.async.cg.shared.global [%0], [%1], 16;\n" :: "r"(s), "l"(src_gmem));
}
__device__ __forceinline__ void cp_commit() { asm volatile("cp.async.commit_group;\n" ::: "memory"); }
template <int N>
__device__ __forceinline__ void cp_wait() { asm volatile("cp.async.wait_group %0;\n" :: "n"(N) : "memory"); }

__device__ __forceinline__ float rna_tf32(float f) {
    uint32_t r;
    asm("cvt.rna.tf32.f32 %0, %1;" : "=r"(r) : "f"(f));
    return __uint_as_float(r);
}

__device__ __forceinline__ void mma_tf32(float c[4], const uint32_t a[4], const uint32_t b[2]) {
    asm volatile(
        "mma.sync.aligned.m16n8k8.row.col.f32.tf32.tf32.f32 "
        "{%0,%1,%2,%3}, {%4,%5,%6,%7}, {%8,%9}, {%0,%1,%2,%3};\n"
        : "+f"(c[0]), "+f"(c[1]), "+f"(c[2]), "+f"(c[3])
        : "r"(a[0]), "r"(a[1]), "r"(a[2]), "r"(a[3]), "r"(b[0]), "r"(b[1]));
}

// ---------------- prepack kernels ----------------
// k-group permutation: [k0,k4,k1,k5,k2,k6,k3,k7] so lane t4 reads (k=t4, k=t4+4) as one float2.
__global__ void k_round_x(const float* __restrict__ x) {
    size_t gidx = (size_t)blockIdx.x * blockDim.x + threadIdx.x;   // one 8-float group each
    const float4* src = (const float4*)x + gidx * 2;
    float4 a = src[0], b = src[1];
    float4 o0 = make_float4(rna_tf32(a.x), rna_tf32(b.x), rna_tf32(a.y), rna_tf32(b.y));
    float4 o1 = make_float4(rna_tf32(a.z), rna_tf32(b.z), rna_tf32(a.w), rna_tf32(b.w));
    float4* dst = (float4*)g_xr + gidx * 2;
    dst[0] = o0; dst[1] = o1;
}

__global__ void k_pack_w(const float* __restrict__ W1, const float* __restrict__ Wc) {
    size_t gidx = (size_t)blockIdx.x * blockDim.x + threadIdx.x;   // n*128 + kgroup
    int n  = (int)(gidx >> 7);
    int kg = (int)(gidx & 127);
    const float* src;
    if (n < 1024)       src = W1 + (size_t)n * 1024;
    else if (n < 2048)  src = Wc + (size_t)(n - 1024) * 2048;            // ctx half
    else                src = Wc + (size_t)(n - 2048) * 2048 + 1024;     // x half
    const float4* s4 = (const float4*)(src + kg * 8);
    float4 a = s4[0], b = s4[1];
    float4 o0 = make_float4(rna_tf32(a.x), rna_tf32(b.x), rna_tf32(a.y), rna_tf32(b.y));
    float4 o1 = make_float4(rna_tf32(a.z), rna_tf32(b.z), rna_tf32(a.w), rna_tf32(b.w));
    float4* dst = (float4*)(g_wr + gidx * 8);
    dst[0] = o0; dst[1] = o1;
}

// ---------------- fused GEMM ----------------
// C[32768, 3072] = g_xr @ g_wr^T  (tf32 mma.sync)
// n-tiles 0-3: s += sum tanh(c+b1)*w2 ; 4-7: y1 = c ; 8-11: y2 = c
__global__ __launch_bounds__(NTH, 1)
void gemm_big(const float* __restrict__ b1, const float* __restrict__ w2)
{
    extern __shared__ float smem[];

    const int tid  = threadIdx.x;
    const int warp = tid >> 5;             // 0..15
    const int lane = tid & 31;
    const int g    = lane >> 2;            // 0..7
    const int t4   = lane & 3;             // 0..3
    const int wm   = (warp >> 3) * 64;     // 2 warp rows
    const int wn   = (warp & 7) * 32;      // 8 warp cols
    const int m0   = blockIdx.y * BM;
    const int nt   = blockIdx.x;           // 0..11

    const float* asrc0 = g_xr + (size_t)m0 * D_;
    const float* bsrc0 = g_wr + (size_t)nt * BN * D_;

    float acc[4][4][4];
#pragma unroll
    for (int mf = 0; mf < 4; mf++)
#pragma unroll
        for (int nf = 0; nf < 4; nf++)
#pragma unroll
            for (int i = 0; i < 4; i++) acc[mf][nf][i] = 0.f;

    // loader: A 128 rows x 4 chunks (512 ops -> 1/thread), B 256 rows x 4 chunks (2/thread)
    const int lr = tid >> 2;               // 0..127
    const int lc = (tid & 3) * 4;          // 0,4,8,12

    // prologue: stages 0..NS-2
#pragma unroll
    for (int s = 0; s < NS - 1; s++) {
        float* As = smem + s * STGF;
        float* Bs = As + BM * SKF;
        const int k0 = s * BK;
        cp16(As + lr * SKF + lc, asrc0 + (size_t)lr * D_ + k0 + lc);
#pragma unroll
        for (int i = 0; i < 2; i++) {
            int row = lr + 128 * i;
            cp16(Bs + row * SKF + lc, bsrc0 + (size_t)row * D_ + k0 + lc);
        }
        cp_commit();
    }

    for (int kt = 0; kt < KT; kt++) {
        cp_wait<NS - 2>();
        __syncthreads();

        const float* As = smem + (kt % NS) * STGF;
        const float* Bs = As + BM * SKF;

#pragma unroll
        for (int kk = 0; kk < BK; kk += 8) {
            uint32_t af[4][4], bf[4][2];
#pragma unroll
            for (int mf = 0; mf < 4; mf++) {
                const float2 v0 = *(const float2*)(As + (wm + mf * 16 + g) * SKF + kk + 2 * t4);
                const float2 v1 = *(const float2*)(As + (wm + mf * 16 + g + 8) * SKF + kk + 2 * t4);
                af[mf][0] = __float_as_uint(v0.x);
                af[mf][1] = __float_as_uint(v1.x);
                af[mf][2] = __float_as_uint(v0.y);
                af[mf][3] = __float_as_uint(v1.y);
            }
#pragma unroll
            for (int nf = 0; nf < 4; nf++) {
                const float2 v = *(const float2*)(Bs + (wn + nf * 8 + g) * SKF + kk + 2 * t4);
                bf[nf][0] = __float_as_uint(v.x);
                bf[nf][1] = __float_as_uint(v.y);
            }
#pragma unroll
            for (int mf = 0; mf < 4; mf++)
#pragma unroll
                for (int nf = 0; nf < 4; nf++)
                    mma_tf32(acc[mf][nf], af[mf], bf[nf]);
        }

        // refill stage computed last iteration (safe: behind this iter's barrier)
        const int kn = kt + NS - 1;
        if (kn < KT) {
            float* Asw = smem + (kn % NS) * STGF;
            float* Bsw = Asw + BM * SKF;
            const int k0 = kn * BK;
            cp16(Asw + lr * SKF + lc, asrc0 + (size_t)lr * D_ + k0 + lc);
#pragma unroll
            for (int i = 0; i < 2; i++) {
                int row = lr + 128 * i;
                cp16(Bsw + row * SKF + lc, bsrc0 + (size_t)row * D_ + k0 + lc);
            }
        }
        cp_commit();
    }

    // ---------------- epilogue ----------------
    if (nt < 4) {
        // s[t] += sum over this block's 256 columns of tanh(c + b1) * w2
        __syncthreads();
        float* s_sm = smem;
        if (tid < BM) s_sm[tid] = 0.f;
        __syncthreads();
#pragma unroll
        for (int mf = 0; mf < 4; mf++) {
            float lo = 0.f, hi = 0.f;
#pragma unroll
            for (int nf = 0; nf < 4; nf++) {
                int col = nt * 256 + wn + nf * 8 + 2 * t4;
                float bb0 = __ldg(b1 + col), bb1 = __ldg(b1 + col + 1);
                float ww0 = __ldg(w2 + col), ww1 = __ldg(w2 + col + 1);
                lo += tanhf(acc[mf][nf][0] + bb0) * ww0 + tanhf(acc[mf][nf][1] + bb1) * ww1;
                hi += tanhf(acc[mf][nf][2] + bb0) * ww0 + tanhf(acc[mf][nf][3] + bb1) * ww1;
            }
            lo += __shfl_xor_sync(0xffffffffu, lo, 1);
            lo += __shfl_xor_sync(0xffffffffu, lo, 2);
            hi += __shfl_xor_sync(0xffffffffu, hi, 1);
            hi += __shfl_xor_sync(0xffffffffu, hi, 2);
            if (t4 == 0) {
                atomicAdd(&s_sm[wm + mf * 16 + g], lo);
                atomicAdd(&s_sm[wm + mf * 16 + g + 8], hi);
            }
        }
        __syncthreads();
        if (tid < BM) atomicAdd(&g_s[m0 + tid], s_sm[tid]);
    } else {
        float* y = (nt < 8) ? g_y1 : g_y2;
        const int c0 = (nt - ((nt < 8) ? 4 : 8)) * 256;
#pragma unroll
        for (int mf = 0; mf < 4; mf++) {
            int row = m0 + wm + mf * 16 + g;
#pragma unroll
            for (int nf = 0; nf < 4; nf++) {
                int col = c0 + wn + nf * 8 + 2 * t4;
                *(float2*)(y + (size_t)row * D_ + col)       = make_float2(acc[mf][nf][0], acc[mf][nf][1]);
                *(float2*)(y + (size_t)(row + 8) * D_ + col) = make_float2(acc[mf][nf][2], acc[mf][nf][3]);
            }
        }
    }
}

// ---------------- scalar pipeline ----------------
__global__ void k_init_s(const float* __restrict__ b2) {
    int i = blockIdx.x * blockDim.x + threadIdx.x;
    if (i < BT_) g_s[i] = b2[0];
}

__global__ void k_maxexp() {
    __shared__ float red[256];
    const int b = blockIdx.x;
    const float* s = g_s + b * T_;
    float m = -1e30f;
    for (int i = threadIdx.x; i < T_; i += 256) m = fmaxf(m, s[i]);
    red[threadIdx.x] = m;
    __syncthreads();
    for (int st = 128; st > 0; st >>= 1) {
        if (threadIdx.x < st) red[threadIdx.x] = fmaxf(red[threadIdx.x], red[threadIdx.x + st]);
        __syncthreads();
    }
    m = red[0];
    for (int i = threadIdx.x; i < T_; i += 256) g_e[b * T_ + i] = expf(s[i] - m);
}

__global__ void k_partial() {
    __shared__ float e_sh[TT];
    const int tile = blockIdx.x, b = blockIdx.y, tid = threadIdx.x;
    const int t0 = tile * TT;
    if (tid < TT) e_sh[tid] = g_e[b * T_ + t0 + tid];
    __syncthreads();
    const int d0 = tid * 4;
    const float4* yp = (const float4*)(g_y1 + (size_t)(b * T_ + t0) * D_ + d0);
    float4 acc = make_float4(0.f, 0.f, 0.f, 0.f);
#pragma unroll 4
    for (int t = 0; t < TT; t++) {
        float4 yv = yp[t * (D_ / 4)];
        float e = e_sh[t];
        acc.x += e * yv.x; acc.y += e * yv.y; acc.z += e * yv.z; acc.w += e * yv.w;
    }
    *(float4*)(g_pex + (size_t)(b * NTILE + tile) * D_ + d0) = acc;
    if (tid == 0) {
        float se = 0.f;
        for (int t = 0; t < TT; t++) se += e_sh[t];
        g_pe[b * NTILE + tile] = se;
    }
}

// exclusive scan across tiles; grid (B_, 4), one d-column per thread (coalesced)
__global__ void k_scan() {
    const int b = blockIdx.x;
    const int d = blockIdx.y * 256 + threadIdx.x;
    float run = 0.f;
#pragma unroll 8
    for (int tile = 0; tile < NTILE; tile++) {
        float* p = g_pex + (size_t)(b * NTILE + tile) * D_ + d;
        float v = *p;
        *p = run;
        run += v;
    }
    if (blockIdx.y == 0 && threadIdx.x == 0) {
        float r = 0.f;
        for (int tile = 0; tile < NTILE; tile++) {
            float v = g_pe[b * NTILE + tile];
            g_pe[b * NTILE + tile] = r;
            r += v;
        }
    }
}

__global__ void k_final(const float* __restrict__ bc, float* __restrict__ out) {
    __shared__ float e_sh[TT], den_sh[TT];
    const int tile = blockIdx.x, b = blockIdx.y, tid = threadIdx.x;
    const int t0 = tile * TT;
    if (tid < TT) e_sh[tid] = g_e[b * T_ + t0 + tid];
    __syncthreads();
    if (tid == 0) {
        float r = g_pe[b * NTILE + tile];
        for (int t = 0; t < TT; t++) { r += e_sh[t]; den_sh[t] = r; }
    }
    __syncthreads();
    const int d0 = tid * 4;
    float4 run = *(float4*)(g_pex + (size_t)(b * NTILE + tile) * D_ + d0);
    float4 bcv = *(const float4*)(bc + d0);
    const float4* y1p = (const float4*)(g_y1 + (size_t)(b * T_ + t0) * D_ + d0);
    const float4* y2p = (const float4*)(g_y2 + (size_t)(b * T_ + t0) * D_ + d0);
    float4* op = (float4*)(out + (size_t)(b * T_ + t0) * D_ + d0);
#pragma unroll 4
    for (int t = 0; t < TT; t++) {
        float4 y1v = y1p[t * (D_ / 4)];
        float4 y2v = y2p[t * (D_ / 4)];
        float e = e_sh[t];
        run.x += e * y1v.x; run.y += e * y1v.y; run.z += e * y1v.z; run.w += e * y1v.w;
        float inv = 1.0f / den_sh[t];
        float4 o;
        o.x = tanhf(run.x * inv + y2v.x + bcv.x);
        o.y = tanhf(run.y * inv + y2v.y + bcv.y);
        o.z = tanhf(run.z * inv + y2v.z + bcv.z);
        o.w = tanhf(run.w * inv + y2v.w + bcv.w);
        op[t * (D_ / 4)] = o;
    }
}

// ---------------- launch ----------------
extern "C" void kernel_launch(void* const* d_in, const int* in_sizes, int n_in,
                              void* d_out, int out_size)
{
    const float* x  = (const float*)d_in[0];
    const float* W1 = (const float*)d_in[1];
    const float* b1 = (const float*)d_in[2];
    const float* w2 = (const float*)d_in[3];
    const float* b2 = (const float*)d_in[4];
    const float* Wc = (const float*)d_in[5];
    const float* bc = (const float*)d_in[6];
    float* out = (float*)d_out;

    cudaFuncSetAttribute(gemm_big, cudaFuncAttributeMaxDynamicSharedMemorySize, SMEM_BYTES);

    k_round_x<<<(BT_ * (D_ / 8)) / 256, 256>>>(x);
    k_pack_w<<<(NBIG * (D_ / 8)) / 256, 256>>>(W1, Wc);
    k_init_s<<<BT_ / 256, 256>>>(b2);

    dim3 gg(NBIG / BN, BT_ / BM);   // (12, 256)
    gemm_big<<<gg, NTH, SMEM_BYTES>>>(b1, w2);

    k_maxexp<<<B_, 256>>>();

    dim3 gp(NTILE, B_);
    k_partial<<<gp, 256>>>();
    dim3 gs(B_, 4);
    k_scan<<<gs, 256>>>();
    k_final<<<gp, 256>>>(bc, out);
}

// round 8
// speedup vs baseline: 1.4697x; 1.4697x over previous
#include <cuda_runtime.h>
#include <cstdint>
#include <cstddef>

// Problem dims
#define B_   8
#define T_   4096
#define D_   1024
#define BT_  (B_ * T_)          // 32768 rows
#define NBIG 3072               // W1(1024) + Wc1(1024) + Wc2(1024)

// GEMM tiling: 128x256 CTA tile, 8 warps of 64x64, K-step 32, 3-stage pipeline
#define BM   128
#define BN   256
#define BK   32
#define KT   (D_ / BK)          // 32 k-iterations
#define NS   3
#define NTH  256
#define SKF  40                 // smem row stride in floats (160B)
#define STGF ((BM + BN) * SKF)  // floats per stage = 15360
#define SMEM_BYTES (NS * STGF * 4)   // 184320

// scan tiling
#define TT    64
#define NTILE (T_ / TT)

// ---------------- scratch ----------------
__device__ __align__(256) float g_s[BT_];
__device__ __align__(256) float g_e[BT_];
__device__ __align__(256) float g_pex[B_ * NTILE * D_];
__device__ __align__(256) float g_pe[B_ * NTILE];
__device__ __align__(256) float g_y1[(size_t)BT_ * D_];          // x @ Wc1^T
__device__ __align__(256) float g_y2[(size_t)BT_ * D_];          // x @ Wc2^T
__device__ __align__(256) float g_xr[(size_t)BT_ * D_];          // x, tf32-rounded, k-permuted
__device__ __align__(256) float g_wr[(size_t)NBIG * D_];         // [W1;Wc1;Wc2], rounded, permuted

// ---------------- PTX helpers ----------------
__device__ __forceinline__ void cp16(void* dst_smem, const void* src_gmem) {
    uint32_t s = (uint32_t)__cvta_generic_to_shared(dst_smem);
    asm volatile("cp.async.cg.shared.global [%0], [%1], 16;\n" :: "r"(s), "l"(src_gmem));
}
__device__ __forceinline__ void cp_commit() { asm volatile("cp.async.commit_group;\n" ::: "memory"); }
template <int N>
__device__ __forceinline__ void cp_wait() { asm volatile("cp.async.wait_group %0;\n" :: "n"(N) : "memory"); }

__device__ __forceinline__ float rna_tf32(float f) {
    uint32_t r;
    asm("cvt.rna.tf32.f32 %0, %1;" : "=r"(r) : "f"(f));
    return __uint_as_float(r);
}

__device__ __forceinline__ void mma_tf32(float c[4], const uint32_t a[4], const uint32_t b[2]) {
    asm volatile(
        "mma.sync.aligned.m16n8k8.row.col.f32.tf32.tf32.f32 "
        "{%0,%1,%2,%3}, {%4,%5,%6,%7}, {%8,%9}, {%0,%1,%2,%3};\n"
        : "+f"(c[0]), "+f"(c[1]), "+f"(c[2]), "+f"(c[3])
        : "r"(a[0]), "r"(a[1]), "r"(a[2]), "r"(a[3]), "r"(b[0]), "r"(b[1]));
}

// ---------------- prepack kernels ----------------
// k-group permutation: [k0,k4,k1,k5,k2,k6,k3,k7] so lane t4 reads (k=t4, k=t4+4) as one float2.
__global__ void k_round_x(const float* __restrict__ x) {
    size_t gidx = (size_t)blockIdx.x * blockDim.x + threadIdx.x;   // one 8-float group each
    const float4* src = (const float4*)x + gidx * 2;
    float4 a = src[0], b = src[1];
    float4 o0 = make_float4(rna_tf32(a.x), rna_tf32(b.x), rna_tf32(a.y), rna_tf32(b.y));
    float4 o1 = make_float4(rna_tf32(a.z), rna_tf32(b.z), rna_tf32(a.w), rna_tf32(b.w));
    float4* dst = (float4*)g_xr + gidx * 2;
    dst[0] = o0; dst[1] = o1;
}

__global__ void k_pack_w(const float* __restrict__ W1, const float* __restrict__ Wc) {
    size_t gidx = (size_t)blockIdx.x * blockDim.x + threadIdx.x;   // n*128 + kgroup
    int n  = (int)(gidx >> 7);
    int kg = (int)(gidx & 127);
    const float* src;
    if (n < 1024)       src = W1 + (size_t)n * 1024;
    else if (n < 2048)  src = Wc + (size_t)(n - 1024) * 2048;            // ctx half
    else                src = Wc + (size_t)(n - 2048) * 2048 + 1024;     // x half
    const float4* s4 = (const float4*)(src + kg * 8);
    float4 a = s4[0], b = s4[1];
    float4 o0 = make_float4(rna_tf32(a.x), rna_tf32(b.x), rna_tf32(a.y), rna_tf32(b.y));
    float4 o1 = make_float4(rna_tf32(a.z), rna_tf32(b.z), rna_tf32(a.w), rna_tf32(b.w));
    float4* dst = (float4*)(g_wr + gidx * 8);
    dst[0] = o0; dst[1] = o1;
}

// ---------------- fused GEMM ----------------
// C[32768, 3072] = g_xr @ g_wr^T  (tf32 mma.sync)
// n-tiles 0-3: s += sum tanh(c+b1)*w2 ; 4-7: y1 = c ; 8-11: y2 = c
__global__ __launch_bounds__(NTH, 1)
void gemm_big(const float* __restrict__ b1, const float* __restrict__ w2)
{
    extern __shared__ float smem[];

    const int tid  = threadIdx.x;
    const int warp = tid >> 5;             // 0..7
    const int lane = tid & 31;
    const int g    = lane >> 2;            // 0..7
    const int t4   = lane & 3;             // 0..3
    const int wm   = (warp >> 2) * 64;     // 2 warp rows
    const int wn   = (warp & 3) * 64;      // 4 warp cols
    const int m0   = blockIdx.y * BM;
    const int nt   = blockIdx.x;           // 0..11

    const float* asrc0 = g_xr + (size_t)m0 * D_;
    const float* bsrc0 = g_wr + (size_t)nt * BN * D_;

    float acc[4][8][4];
#pragma unroll
    for (int mf = 0; mf < 4; mf++)
#pragma unroll
        for (int nf = 0; nf < 8; nf++)
#pragma unroll
            for (int i = 0; i < 4; i++) acc[mf][nf][i] = 0.f;

    // prologue: stages 0..NS-2
#pragma unroll
    for (int s = 0; s < NS - 1; s++) {
        float* As = smem + s * STGF;
        float* Bs = As + BM * SKF;
        const int k0 = s * BK;
#pragma unroll
        for (int i = 0; i < 4; i++) {               // A: 128 rows x 8 chunks
            int c = tid + 256 * i;
            int row = c >> 3, col = (c & 7) * 4;
            cp16(As + row * SKF + col, asrc0 + (size_t)row * D_ + k0 + col);
        }
#pragma unroll
        for (int i = 0; i < 8; i++) {               // B: 256 rows x 8 chunks
            int c = tid + 256 * i;
            int row = c >> 3, col = (c & 7) * 4;
            cp16(Bs + row * SKF + col, bsrc0 + (size_t)row * D_ + k0 + col);
        }
        cp_commit();
    }

    for (int kt = 0; kt < KT; kt++) {
        cp_wait<NS - 2>();
        __syncthreads();

        // refill stage freed by last iteration's compute, BEFORE this compute
        const int kn = kt + NS - 1;
        if (kn < KT) {
            float* Asw = smem + (kn % NS) * STGF;
            float* Bsw = Asw + BM * SKF;
            const int k0 = kn * BK;
#pragma unroll
            for (int i = 0; i < 4; i++) {
                int c = tid + 256 * i;
                int row = c >> 3, col = (c & 7) * 4;
                cp16(Asw + row * SKF + col, asrc0 + (size_t)row * D_ + k0 + col);
            }
#pragma unroll
            for (int i = 0; i < 8; i++) {
                int c = tid + 256 * i;
                int row = c >> 3, col = (c & 7) * 4;
                cp16(Bsw + row * SKF + col, bsrc0 + (size_t)row * D_ + k0 + col);
            }
        }
        cp_commit();

        const float* As = smem + (kt % NS) * STGF;
        const float* Bs = As + BM * SKF;

#pragma unroll
        for (int kk = 0; kk < BK; kk += 8) {
            uint32_t af[4][4], bf[8][2];
#pragma unroll
            for (int mf = 0; mf < 4; mf++) {
                const float2 v0 = *(const float2*)(As + (wm + mf * 16 + g) * SKF + kk + 2 * t4);
                const float2 v1 = *(const float2*)(As + (wm + mf * 16 + g + 8) * SKF + kk + 2 * t4);
                af[mf][0] = __float_as_uint(v0.x);
                af[mf][1] = __float_as_uint(v1.x);
                af[mf][2] = __float_as_uint(v0.y);
                af[mf][3] = __float_as_uint(v1.y);
            }
#pragma unroll
            for (int nf = 0; nf < 8; nf++) {
                const float2 v = *(const float2*)(Bs + (wn + nf * 8 + g) * SKF + kk + 2 * t4);
                bf[nf][0] = __float_as_uint(v.x);
                bf[nf][1] = __float_as_uint(v.y);
            }
#pragma unroll
            for (int mf = 0; mf < 4; mf++)
#pragma unroll
                for (int nf = 0; nf < 8; nf++)
                    mma_tf32(acc[mf][nf], af[mf], bf[nf]);
        }
    }

    // ---------------- epilogue ----------------
    if (nt < 4) {
        // s[t] += sum over this block's 256 columns of tanh(c + b1) * w2
        __syncthreads();
        float* s_sm = smem;
        if (tid < BM) s_sm[tid] = 0.f;
        __syncthreads();
#pragma unroll
        for (int mf = 0; mf < 4; mf++) {
            float lo = 0.f, hi = 0.f;
#pragma unroll
            for (int nf = 0; nf < 8; nf++) {
                int col = nt * 256 + wn + nf * 8 + 2 * t4;
                float bb0 = __ldg(b1 + col), bb1 = __ldg(b1 + col + 1);
                float ww0 = __ldg(w2 + col), ww1 = __ldg(w2 + col + 1);
                lo += tanhf(acc[mf][nf][0] + bb0) * ww0 + tanhf(acc[mf][nf][1] + bb1) * ww1;
                hi += tanhf(acc[mf][nf][2] + bb0) * ww0 + tanhf(acc[mf][nf][3] + bb1) * ww1;
            }
            lo += __shfl_xor_sync(0xffffffffu, lo, 1);
            lo += __shfl_xor_sync(0xffffffffu, lo, 2);
            hi += __shfl_xor_sync(0xffffffffu, hi, 1);
            hi += __shfl_xor_sync(0xffffffffu, hi, 2);
            if (t4 == 0) {
                atomicAdd(&s_sm[wm + mf * 16 + g], lo);
                atomicAdd(&s_sm[wm + mf * 16 + g + 8], hi);
            }
        }
        __syncthreads();
        if (tid < BM) atomicAdd(&g_s[m0 + tid], s_sm[tid]);
    } else {
        float* y = (nt < 8) ? g_y1 : g_y2;
        const int c0 = (nt - ((nt < 8) ? 4 : 8)) * 256;
#pragma unroll
        for (int mf = 0; mf < 4; mf++) {
            int row = m0 + wm + mf * 16 + g;
#pragma unroll
            for (int nf = 0; nf < 8; nf++) {
                int col = c0 + wn + nf * 8 + 2 * t4;
                *(float2*)(y + (size_t)row * D_ + col)       = make_float2(acc[mf][nf][0], acc[mf][nf][1]);
                *(float2*)(y + (size_t)(row + 8) * D_ + col) = make_float2(acc[mf][nf][2], acc[mf][nf][3]);
            }
        }
    }
}

// ---------------- scalar pipeline ----------------
__global__ void k_init_s(const float* __restrict__ b2) {
    int i = blockIdx.x * blockDim.x + threadIdx.x;
    if (i < BT_) g_s[i] = b2[0];
}

__global__ void k_maxexp() {
    __shared__ float red[256];
    const int b = blockIdx.x;
    const float* s = g_s + b * T_;
    float m = -1e30f;
    for (int i = threadIdx.x; i < T_; i += 256) m = fmaxf(m, s[i]);
    red[threadIdx.x] = m;
    __syncthreads();
    for (int st = 128; st > 0; st >>= 1) {
        if (threadIdx.x < st) red[threadIdx.x] = fmaxf(red[threadIdx.x], red[threadIdx.x + st]);
        __syncthreads();
    }
    m = red[0];
    for (int i = threadIdx.x; i < T_; i += 256) g_e[b * T_ + i] = expf(s[i] - m);
}

__global__ void k_partial() {
    __shared__ float e_sh[TT];
    const int tile = blockIdx.x, b = blockIdx.y, tid = threadIdx.x;
    const int t0 = tile * TT;
    if (tid < TT) e_sh[tid] = g_e[b * T_ + t0 + tid];
    __syncthreads();
    const int d0 = tid * 4;
    const float4* yp = (const float4*)(g_y1 + (size_t)(b * T_ + t0) * D_ + d0);
    float4 acc = make_float4(0.f, 0.f, 0.f, 0.f);
#pragma unroll 4
    for (int t = 0; t < TT; t++) {
        float4 yv = yp[t * (D_ / 4)];
        float e = e_sh[t];
        acc.x += e * yv.x; acc.y += e * yv.y; acc.z += e * yv.z; acc.w += e * yv.w;
    }
    *(float4*)(g_pex + (size_t)(b * NTILE + tile) * D_ + d0) = acc;
    if (tid == 0) {
        float se = 0.f;
        for (int t = 0; t < TT; t++) se += e_sh[t];
        g_pe[b * NTILE + tile] = se;
    }
}

// exclusive scan across tiles; grid (B_, 4), one d-column per thread (coalesced)
__global__ void k_scan() {
    const int b = blockIdx.x;
    const int d = blockIdx.y * 256 + threadIdx.x;
    float run = 0.f;
#pragma unroll 8
    for (int tile = 0; tile < NTILE; tile++) {
        float* p = g_pex + (size_t)(b * NTILE + tile) * D_ + d;
        float v = *p;
        *p = run;
        run += v;
    }
    if (blockIdx.y == 0 && threadIdx.x == 0) {
        float r = 0.f;
        for (int tile = 0; tile < NTILE; tile++) {
            float v = g_pe[b * NTILE + tile];
            g_pe[b * NTILE + tile] = r;
            r += v;
        }
    }
}

__global__ void k_final(const float* __restrict__ bc, float* __restrict__ out) {
    __shared__ float e_sh[TT], den_sh[TT];
    const int tile = blockIdx.x, b = blockIdx.y, tid = threadIdx.x;
    const int t0 = tile * TT;
    if (tid < TT) e_sh[tid] = g_e[b * T_ + t0 + tid];
    __syncthreads();
    if (tid == 0) {
        float r = g_pe[b * NTILE + tile];
        for (int t = 0; t < TT; t++) { r += e_sh[t]; den_sh[t] = r; }
    }
    __syncthreads();
    const int d0 = tid * 4;
    float4 run = *(float4*)(g_pex + (size_t)(b * NTILE + tile) * D_ + d0);
    float4 bcv = *(const float4*)(bc + d0);
    const float4* y1p = (const float4*)(g_y1 + (size_t)(b * T_ + t0) * D_ + d0);
    const float4* y2p = (const float4*)(g_y2 + (size_t)(b * T_ + t0) * D_ + d0);
    float4* op = (float4*)(out + (size_t)(b * T_ + t0) * D_ + d0);
#pragma unroll 4
    for (int t = 0; t < TT; t++) {
        float4 y1v = y1p[t * (D_ / 4)];
        float4 y2v = y2p[t * (D_ / 4)];
        float e = e_sh[t];
        run.x += e * y1v.x; run.y += e * y1v.y; run.z += e * y1v.z; run.w += e * y1v.w;
        float inv = 1.0f / den_sh[t];
        float4 o;
        o.x = tanhf(run.x * inv + y2v.x + bcv.x);
        o.y = tanhf(run.y * inv + y2v.y + bcv.y);
        o.z = tanhf(run.z * inv + y2v.z + bcv.z);
        o.w = tanhf(run.w * inv + y2v.w + bcv.w);
        op[t * (D_ / 4)] = o;
    }
}

// ---------------- launch ----------------
extern "C" void kernel_launch(void* const* d_in, const int* in_sizes, int n_in,
                              void* d_out, int out_size)
{
    const float* x  = (const float*)d_in[0];
    const float* W1 = (const float*)d_in[1];
    const float* b1 = (const float*)d_in[2];
    const float* w2 = (const float*)d_in[3];
    const float* b2 = (const float*)d_in[4];
    const float* Wc = (const float*)d_in[5];
    const float* bc = (const float*)d_in[6];
    float* out = (float*)d_out;

    cudaFuncSetAttribute(gemm_big, cudaFuncAttributeMaxDynamicSharedMemorySize, SMEM_BYTES);

    k_round_x<<<(BT_ * (D_ / 8)) / 256, 256>>>(x);
    k_pack_w<<<(NBIG * (D_ / 8)) / 256, 256>>>(W1, Wc);
    k_init_s<<<BT_ / 256, 256>>>(b2);

    dim3 gg(NBIG / BN, BT_ / BM);   // (12, 256)
    gemm_big<<<gg, NTH, SMEM_BYTES>>>(b1, w2);

    k_maxexp<<<B_, 256>>>();

    dim3 gp(NTILE, B_);
    k_partial<<<gp, 256>>>();
    dim3 gs(B_, 4);
    k_scan<<<gs, 256>>>();
    k_final<<<gp, 256>>>(bc, out);
}

// round 12
// speedup vs baseline: 2.3361x; 1.5895x over previous
#include <cuda_runtime.h>
#include <cuda_fp16.h>
#include <cstdint>
#include <cstddef>

// Problem dims
#define B_   8
#define T_   4096
#define D_   1024
#define BT_  (B_ * T_)          // 32768 rows
#define NBIG 3072               // W1(1024) + Wc1(1024) + Wc2(1024)

// GEMM tiling: 128x256 CTA tile, 8 warps of 64x64, K-step 32 (fp16 m16n8k16), 4 stages
#define BM   128
#define BN   256
#define BK   32
#define KT   (D_ / BK)          // 32 k-iterations
#define NS   4
#define NTH  256
#define SKH  48                 // smem row stride in halves (96B) -> conflict-free LDS.64
#define STGH ((BM + BN) * SKH)  // halves per stage = 18432 (36864 B)
#define SMEM_BYTES (NS * STGH * 2)   // 147456

// scan tiling
#define TT    64
#define NTILE (T_ / TT)

// ---------------- scratch ----------------
__device__ __align__(256) float g_s[BT_];
__device__ __align__(256) float g_e[BT_];
__device__ __align__(256) float g_pex[B_ * NTILE * D_];
__device__ __align__(256) float g_pe[B_ * NTILE];
__device__ __align__(256) float g_y1[(size_t)BT_ * D_];          // x @ Wc1^T
__device__ __align__(256) float g_y2[(size_t)BT_ * D_];          // x @ Wc2^T
__device__ __align__(256) __half g_xh[(size_t)BT_ * D_];         // x, fp16, k-permuted
__device__ __align__(256) __half g_wh[(size_t)NBIG * D_];        // [W1;Wc1;Wc2], fp16, permuted

// ---------------- PTX helpers ----------------
__device__ __forceinline__ void cp16(void* dst_smem, const void* src_gmem) {
    uint32_t s = (uint32_t)__cvta_generic_to_shared(dst_smem);
    asm volatile("cp.async.cg.shared.global [%0], [%1], 16;\n" :: "r"(s), "l"(src_gmem));
}
__device__ __forceinline__ void cp_commit() { asm volatile("cp.async.commit_group;\n" ::: "memory"); }
template <int N>
__device__ __forceinline__ void cp_wait() { asm volatile("cp.async.wait_group %0;\n" :: "n"(N) : "memory"); }

__device__ __forceinline__ void mma_f16(float c[4], const uint32_t a[4], const uint32_t b[2]) {
    asm volatile(
        "mma.sync.aligned.m16n8k16.row.col.f32.f16.f16.f32 "
        "{%0,%1,%2,%3}, {%4,%5,%6,%7}, {%8,%9}, {%0,%1,%2,%3};\n"
        : "+f"(c[0]), "+f"(c[1]), "+f"(c[2]), "+f"(c[3])
        : "r"(a[0]), "r"(a[1]), "r"(a[2]), "r"(a[3]), "r"(b[0]), "r"(b[1]));
}

// pack two fp32 -> one u32 holding (lo=f0, hi=f1) as fp16
__device__ __forceinline__ uint32_t pack_h2(float f0, float f1) {
    uint16_t lo = __half_as_ushort(__float2half_rn(f0));
    uint16_t hi = __half_as_ushort(__float2half_rn(f1));
    return (uint32_t)lo | ((uint32_t)hi << 16);
}

// ---------------- prepack kernels ----------------
// per-16-group permutation [0,1,8,9, 2,3,10,11, 4,5,12,13, 6,7,14,15]:
// lane t4's fragment pair (k=2t4,2t4+1,2t4+8,2t4+9) becomes 8 contiguous bytes.
__device__ __forceinline__ void pack16(const float4* s4, uint4* dst) {
    float4 i0 = s4[0], i1 = s4[1], i2 = s4[2], i3 = s4[3];
    uint4 o0, o1;
    o0.x = pack_h2(i0.x, i0.y);   // e0,e1
    o0.y = pack_h2(i2.x, i2.y);   // e8,e9
    o0.z = pack_h2(i0.z, i0.w);   // e2,e3
    o0.w = pack_h2(i2.z, i2.w);   // e10,e11
    o1.x = pack_h2(i1.x, i1.y);   // e4,e5
    o1.y = pack_h2(i3.x, i3.y);   // e12,e13
    o1.z = pack_h2(i1.z, i1.w);   // e6,e7
    o1.w = pack_h2(i3.z, i3.w);   // e14,e15
    dst[0] = o0; dst[1] = o1;
}

__global__ void k_pack_x(const float* __restrict__ x) {
    size_t gidx = (size_t)blockIdx.x * blockDim.x + threadIdx.x;   // one 16-float group
    pack16((const float4*)x + gidx * 4, (uint4*)(g_xh + gidx * 16));
}

__global__ void k_pack_w(const float* __restrict__ W1, const float* __restrict__ Wc) {
    size_t gidx = (size_t)blockIdx.x * blockDim.x + threadIdx.x;   // n*64 + kgroup
    int n  = (int)(gidx >> 6);
    int kg = (int)(gidx & 63);
    const float* src;
    if (n < 1024)       src = W1 + (size_t)n * 1024;
    else if (n < 2048)  src = Wc + (size_t)(n - 1024) * 2048;            // ctx half
    else                src = Wc + (size_t)(n - 2048) * 2048 + 1024;     // x half
    pack16((const float4*)(src + kg * 16), (uint4*)(g_wh + gidx * 16));
}

// ---------------- fused GEMM ----------------
// C[32768, 3072] = g_xh @ g_wh^T  (fp16 mma.sync, fp32 accum)
// n-tiles 0-3: s += sum tanh(c+b1)*w2 ; 4-7: y1 = c ; 8-11: y2 = c
__global__ __launch_bounds__(NTH, 1)
void gemm_big(const float* __restrict__ b1, const float* __restrict__ w2)
{
    extern __shared__ __half smem[];

    const int tid  = threadIdx.x;
    const int warp = tid >> 5;             // 0..7
    const int lane = tid & 31;
    const int g    = lane >> 2;            // 0..7
    const int t4   = lane & 3;             // 0..3
    const int wm   = (warp >> 2) * 64;     // 2 warp rows
    const int wn   = (warp & 3) * 64;      // 4 warp cols
    const int m0   = blockIdx.y * BM;
    const int nt   = blockIdx.x;           // 0..11

    const __half* asrc0 = g_xh + (size_t)m0 * D_;
    const __half* bsrc0 = g_wh + (size_t)nt * BN * D_;

    float acc[4][8][4];
#pragma unroll
    for (int mf = 0; mf < 4; mf++)
#pragma unroll
        for (int nf = 0; nf < 8; nf++)
#pragma unroll
            for (int i = 0; i < 4; i++) acc[mf][nf][i] = 0.f;

    // loader: per stage, A: 128 rows x 4 chunks(16B) = 512 ops, B: 256 x 4 = 1024 ops
    // prologue: stages 0..NS-2
#pragma unroll
    for (int s = 0; s < NS - 1; s++) {
        __half* As = smem + s * STGH;
        __half* Bs = As + BM * SKH;
        const int k0 = s * BK;
#pragma unroll
        for (int i = 0; i < 2; i++) {
            int c = tid + 256 * i;
            int row = c >> 2, col = (c & 3) * 8;
            cp16(As + row * SKH + col, asrc0 + (size_t)row * D_ + k0 + col);
        }
#pragma unroll
        for (int i = 0; i < 4; i++) {
            int c = tid + 256 * i;
            int row = c >> 2, col = (c & 3) * 8;
            cp16(Bs + row * SKH + col, bsrc0 + (size_t)row * D_ + k0 + col);
        }
        cp_commit();
    }

    for (int kt = 0; kt < KT; kt++) {
        cp_wait<NS - 2>();
        __syncthreads();

        // refill stage freed by last iteration's compute, BEFORE this compute
        const int kn = kt + NS - 1;
        if (kn < KT) {
            __half* Asw = smem + (kn % NS) * STGH;
            __half* Bsw = Asw + BM * SKH;
            const int k0 = kn * BK;
#pragma unroll
            for (int i = 0; i < 2; i++) {
                int c = tid + 256 * i;
                int row = c >> 2, col = (c & 3) * 8;
                cp16(Asw + row * SKH + col, asrc0 + (size_t)row * D_ + k0 + col);
            }
#pragma unroll
            for (int i = 0; i < 4; i++) {
                int c = tid + 256 * i;
                int row = c >> 2, col = (c & 3) * 8;
                cp16(Bsw + row * SKH + col, bsrc0 + (size_t)row * D_ + k0 + col);
            }
        }
        cp_commit();

        const __half* As = smem + (kt % NS) * STGH;
        const __half* Bs = As + BM * SKH;

#pragma unroll
        for (int kk = 0; kk < BK; kk += 16) {
            uint32_t af[4][4], bf[8][2];
#pragma unroll
            for (int mf = 0; mf < 4; mf++) {
                const uint2 v0 = *(const uint2*)(As + (wm + mf * 16 + g) * SKH + kk + 4 * t4);
                const uint2 v1 = *(const uint2*)(As + (wm + mf * 16 + g + 8) * SKH + kk + 4 * t4);
                af[mf][0] = v0.x;    // (row g,   k 2t4..2t4+1)
                af[mf][1] = v1.x;    // (row g+8, k 2t4..)
                af[mf][2] = v0.y;    // (row g,   k 2t4+8..)
                af[mf][3] = v1.y;    // (row g+8, k 2t4+8..)
            }
#pragma unroll
            for (int nf = 0; nf < 8; nf++) {
                const uint2 v = *(const uint2*)(Bs + (wn + nf * 8 + g) * SKH + kk + 4 * t4);
                bf[nf][0] = v.x;     // (k 2t4..,   col g)
                bf[nf][1] = v.y;     // (k 2t4+8.., col g)
            }
#pragma unroll
            for (int mf = 0; mf < 4; mf++)
#pragma unroll
                for (int nf = 0; nf < 8; nf++)
                    mma_f16(acc[mf][nf], af[mf], bf[nf]);
        }
    }

    // ---------------- epilogue ----------------
    if (nt < 4) {
        // s[t] += sum over this block's 256 columns of tanh(c + b1) * w2
        __syncthreads();
        float* s_sm = (float*)smem;
        if (tid < BM) s_sm[tid] = 0.f;
        __syncthreads();
#pragma unroll
        for (int mf = 0; mf < 4; mf++) {
            float lo = 0.f, hi = 0.f;
#pragma unroll
            for (int nf = 0; nf < 8; nf++) {
                int col = nt * 256 + wn + nf * 8 + 2 * t4;
                float bb0 = __ldg(b1 + col), bb1 = __ldg(b1 + col + 1);
                float ww0 = __ldg(w2 + col), ww1 = __ldg(w2 + col + 1);
                lo += tanhf(acc[mf][nf][0] + bb0) * ww0 + tanhf(acc[mf][nf][1] + bb1) * ww1;
                hi += tanhf(acc[mf][nf][2] + bb0) * ww0 + tanhf(acc[mf][nf][3] + bb1) * ww1;
            }
            lo += __shfl_xor_sync(0xffffffffu, lo, 1);
            lo += __shfl_xor_sync(0xffffffffu, lo, 2);
            hi += __shfl_xor_sync(0xffffffffu, hi, 1);
            hi += __shfl_xor_sync(0xffffffffu, hi, 2);
            if (t4 == 0) {
                atomicAdd(&s_sm[wm + mf * 16 + g], lo);
                atomicAdd(&s_sm[wm + mf * 16 + g + 8], hi);
            }
        }
        __syncthreads();
        if (tid < BM) atomicAdd(&g_s[m0 + tid], s_sm[tid]);
    } else {
        float* y = (nt < 8) ? g_y1 : g_y2;
        const int c0 = (nt - ((nt < 8) ? 4 : 8)) * 256;
#pragma unroll
        for (int mf = 0; mf < 4; mf++) {
            int row = m0 + wm + mf * 16 + g;
#pragma unroll
            for (int nf = 0; nf < 8; nf++) {
                int col = c0 + wn + nf * 8 + 2 * t4;
                *(float2*)(y + (size_t)row * D_ + col)       = make_float2(acc[mf][nf][0], acc[mf][nf][1]);
                *(float2*)(y + (size_t)(row + 8) * D_ + col) = make_float2(acc[mf][nf][2], acc[mf][nf][3]);
            }
        }
    }
}

// ---------------- scalar pipeline ----------------
__global__ void k_init_s(const float* __restrict__ b2) {
    int i = blockIdx.x * blockDim.x + threadIdx.x;
    if (i < BT_) g_s[i] = b2[0];
}

__global__ void k_maxexp() {
    __shared__ float red[256];
    const int b = blockIdx.x;
    const float* s = g_s + b * T_;
    float m = -1e30f;
    for (int i = threadIdx.x; i < T_; i += 256) m = fmaxf(m, s[i]);
    red[threadIdx.x] = m;
    __syncthreads();
    for (int st = 128; st > 0; st >>= 1) {
        if (threadIdx.x < st) red[threadIdx.x] = fmaxf(red[threadIdx.x], red[threadIdx.x + st]);
        __syncthreads();
    }
    m = red[0];
    for (int i = threadIdx.x; i < T_; i += 256) g_e[b * T_ + i] = expf(s[i] - m);
}

__global__ void k_partial() {
    __shared__ float e_sh[TT];
    const int tile = blockIdx.x, b = blockIdx.y, tid = threadIdx.x;
    const int t0 = tile * TT;
    if (tid < TT) e_sh[tid] = g_e[b * T_ + t0 + tid];
    __syncthreads();
    const int d0 = tid * 4;
    const float4* yp = (const float4*)(g_y1 + (size_t)(b * T_ + t0) * D_ + d0);
    float4 acc = make_float4(0.f, 0.f, 0.f, 0.f);
#pragma unroll 4
    for (int t = 0; t < TT; t++) {
        float4 yv = yp[t * (D_ / 4)];
        float e = e_sh[t];
        acc.x += e * yv.x; acc.y += e * yv.y; acc.z += e * yv.z; acc.w += e * yv.w;
    }
    *(float4*)(g_pex + (size_t)(b * NTILE + tile) * D_ + d0) = acc;
    if (tid == 0) {
        float se = 0.f;
        for (int t = 0; t < TT; t++) se += e_sh[t];
        g_pe[b * NTILE + tile] = se;
    }
}

// exclusive scan across tiles; grid (B_, 4), one d-column per thread (coalesced)
__global__ void k_scan() {
    const int b = blockIdx.x;
    const int d = blockIdx.y * 256 + threadIdx.x;
    float run = 0.f;
#pragma unroll 8
    for (int tile = 0; tile < NTILE; tile++) {
        float* p = g_pex + (size_t)(b * NTILE + tile) * D_ + d;
        float v = *p;
        *p = run;
        run += v;
    }
    if (blockIdx.y == 0 && threadIdx.x == 0) {
        float r = 0.f;
        for (int tile = 0; tile < NTILE; tile++) {
            float v = g_pe[b * NTILE + tile];
            g_pe[b * NTILE + tile] = r;
            r += v;
        }
    }
}

__global__ void k_final(const float* __restrict__ bc, float* __restrict__ out) {
    __shared__ float e_sh[TT], den_sh[TT];
    const int tile = blockIdx.x, b = blockIdx.y, tid = threadIdx.x;
    const int t0 = tile * TT;
    if (tid < TT) e_sh[tid] = g_e[b * T_ + t0 + tid];
    __syncthreads();
    if (tid == 0) {
        float r = g_pe[b * NTILE + tile];
        for (int t = 0; t < TT; t++) { r += e_sh[t]; den_sh[t] = r; }
    }
    __syncthreads();
    const int d0 = tid * 4;
    float4 run = *(float4*)(g_pex + (size_t)(b * NTILE + tile) * D_ + d0);
    float4 bcv = *(const float4*)(bc + d0);
    const float4* y1p = (const float4*)(g_y1 + (size_t)(b * T_ + t0) * D_ + d0);
    const float4* y2p = (const float4*)(g_y2 + (size_t)(b * T_ + t0) * D_ + d0);
    float4* op = (float4*)(out + (size_t)(b * T_ + t0) * D_ + d0);
#pragma unroll 4
    for (int t = 0; t < TT; t++) {
        float4 y1v = y1p[t * (D_ / 4)];
        float4 y2v = y2p[t * (D_ / 4)];
        float e = e_sh[t];
        run.x += e * y1v.x; run.y += e * y1v.y; run.z += e * y1v.z; run.w += e * y1v.w;
        float inv = 1.0f / den_sh[t];
        float4 o;
        o.x = tanhf(run.x * inv + y2v.x + bcv.x);
        o.y = tanhf(run.y * inv + y2v.y + bcv.y);
        o.z = tanhf(run.z * inv + y2v.z + bcv.z);
        o.w = tanhf(run.w * inv + y2v.w + bcv.w);
        op[t * (D_ / 4)] = o;
    }
}

// ---------------- launch ----------------
extern "C" void kernel_launch(void* const* d_in, const int* in_sizes, int n_in,
                              void* d_out, int out_size)
{
    const float* x  = (const float*)d_in[0];
    const float* W1 = (const float*)d_in[1];
    const float* b1 = (const float*)d_in[2];
    const float* w2 = (const float*)d_in[3];
    const float* b2 = (const float*)d_in[4];
    const float* Wc = (const float*)d_in[5];
    const float* bc = (const float*)d_in[6];
    float* out = (float*)d_out;

    cudaFuncSetAttribute(gemm_big, cudaFuncAttributeMaxDynamicSharedMemorySize, SMEM_BYTES);

    k_pack_x<<<(BT_ * (D_ / 16)) / 256, 256>>>(x);                 // 8192 blocks
    k_pack_w<<<(NBIG * (D_ / 16)) / 256, 256>>>(W1, Wc);           // 768 blocks
    k_init_s<<<BT_ / 256, 256>>>(b2);

    dim3 gg(NBIG / BN, BT_ / BM);   // (12, 256)
    gemm_big<<<gg, NTH, SMEM_BYTES>>>(b1, w2);

    k_maxexp<<<B_, 256>>>();

    dim3 gp(NTILE, B_);
    k_partial<<<gp, 256>>>();
    dim3 gs(B_, 4);
    k_scan<<<gs, 256>>>();
    k_final<<<gp, 256>>>(bc, out);
}

// round 15
// speedup vs baseline: 2.3404x; 1.0018x over previous
#include <cuda_runtime.h>
#include <cuda_fp16.h>
#include <cstdint>
#include <cstddef>

// Problem dims
#define B_   8
#define T_   4096
#define D_   1024
#define BT_  (B_ * T_)          // 32768 rows
#define NBIG 3072               // W1(1024) + Wc1(1024) + Wc2(1024)

// GEMM tiling: 128x384 CTA tile, 12 warps of 64x64 (2x6), K-step 32, 3 stages
#define BM   128
#define BN   384
#define BK   32
#define KT   (D_ / BK)          // 32 k-iterations
#define NS   3
#define NTH  384
#define SKH  48                 // smem row stride in halves (96B) -> conflict-free LDS.64
#define STGH ((BM + BN) * SKH)  // halves per stage = 24576 (49152 B)
#define SMEM_BYTES (NS * STGH * 2)   // 147456

// scan tiling
#define TT    64
#define NTILE (T_ / TT)

// ---------------- scratch ----------------
__device__ __align__(256) float g_s[BT_];
__device__ __align__(256) float g_e[BT_];
__device__ __align__(256) float g_pex[B_ * NTILE * D_];
__device__ __align__(256) float g_pe[B_ * NTILE];
__device__ __align__(256) float g_y1[(size_t)BT_ * D_];          // x @ Wc1^T
__device__ __align__(256) float g_y2[(size_t)BT_ * D_];          // x @ Wc2^T
__device__ __align__(256) __half g_xh[(size_t)BT_ * D_];         // x, fp16, k-permuted
__device__ __align__(256) __half g_wh[(size_t)NBIG * D_];        // [W1;Wc1;Wc2], fp16, permuted

// ---------------- PTX helpers ----------------
__device__ __forceinline__ void cp16(void* dst_smem, const void* src_gmem) {
    uint32_t s = (uint32_t)__cvta_generic_to_shared(dst_smem);
    asm volatile("cp.async.cg.shared.global [%0], [%1], 16;\n" :: "r"(s), "l"(src_gmem));
}
__device__ __forceinline__ void cp_commit() { asm volatile("cp.async.commit_group;\n" ::: "memory"); }
template <int N>
__device__ __forceinline__ void cp_wait() { asm volatile("cp.async.wait_group %0;\n" :: "n"(N) : "memory"); }

__device__ __forceinline__ void mma_f16(float c[4], const uint32_t a[4], const uint32_t b[2]) {
    asm volatile(
        "mma.sync.aligned.m16n8k16.row.col.f32.f16.f16.f32 "
        "{%0,%1,%2,%3}, {%4,%5,%6,%7}, {%8,%9}, {%0,%1,%2,%3};\n"
        : "+f"(c[0]), "+f"(c[1]), "+f"(c[2]), "+f"(c[3])
        : "r"(a[0]), "r"(a[1]), "r"(a[2]), "r"(a[3]), "r"(b[0]), "r"(b[1]));
}

// pack two fp32 -> one u32 holding (lo=f0, hi=f1) as fp16
__device__ __forceinline__ uint32_t pack_h2(float f0, float f1) {
    uint16_t lo = __half_as_ushort(__float2half_rn(f0));
    uint16_t hi = __half_as_ushort(__float2half_rn(f1));
    return (uint32_t)lo | ((uint32_t)hi << 16);
}

// ---------------- prepack kernels ----------------
// per-16-group permutation [0,1,8,9, 2,3,10,11, 4,5,12,13, 6,7,14,15]:
// lane t4's fragment pair (k=2t4,2t4+1,2t4+8,2t4+9) becomes 8 contiguous bytes.
__device__ __forceinline__ void pack16(const float4* s4, uint4* dst) {
    float4 i0 = s4[0], i1 = s4[1], i2 = s4[2], i3 = s4[3];
    uint4 o0, o1;
    o0.x = pack_h2(i0.x, i0.y);   // e0,e1
    o0.y = pack_h2(i2.x, i2.y);   // e8,e9
    o0.z = pack_h2(i0.z, i0.w);   // e2,e3
    o0.w = pack_h2(i2.z, i2.w);   // e10,e11
    o1.x = pack_h2(i1.x, i1.y);   // e4,e5
    o1.y = pack_h2(i3.x, i3.y);   // e12,e13
    o1.z = pack_h2(i1.z, i1.w);   // e6,e7
    o1.w = pack_h2(i3.z, i3.w);   // e14,e15
    dst[0] = o0; dst[1] = o1;
}

__global__ void k_pack_x(const float* __restrict__ x) {
    size_t gidx = (size_t)blockIdx.x * blockDim.x + threadIdx.x;   // one 16-float group
    pack16((const float4*)x + gidx * 4, (uint4*)(g_xh + gidx * 16));
}

__global__ void k_pack_w(const float* __restrict__ W1, const float* __restrict__ Wc) {
    size_t gidx = (size_t)blockIdx.x * blockDim.x + threadIdx.x;   // n*64 + kgroup
    int n  = (int)(gidx >> 6);
    int kg = (int)(gidx & 63);
    const float* src;
    if (n < 1024)       src = W1 + (size_t)n * 1024;
    else if (n < 2048)  src = Wc + (size_t)(n - 1024) * 2048;            // ctx half
    else                src = Wc + (size_t)(n - 2048) * 2048 + 1024;     // x half
    pack16((const float4*)(src + kg * 16), (uint4*)(g_wh + gidx * 16));
}

// ---------------- fused GEMM ----------------
// C[32768, 3072] = g_xh @ g_wh^T  (fp16 mma.sync, fp32 accum)
// per-warp region by global column: [0,1024) -> s reduction, [1024,2048) -> y1, [2048,3072) -> y2
__global__ __launch_bounds__(NTH, 1)
void gemm_big(const float* __restrict__ b1, const float* __restrict__ w2)
{
    extern __shared__ __half smem[];

    const int tid  = threadIdx.x;
    const int warp = tid >> 5;             // 0..11
    const int lane = tid & 31;
    const int g    = lane >> 2;            // 0..7
    const int t4   = lane & 3;             // 0..3
    const int wm   = (warp >= 6) ? 64 : 0; // 2 warp rows
    const int wn   = (warp % 6) * 64;      // 6 warp cols
    const int m0   = blockIdx.y * BM;
    const int nt   = blockIdx.x;           // 0..7

    const __half* asrc0 = g_xh + (size_t)m0 * D_;
    const __half* bsrc0 = g_wh + (size_t)nt * BN * D_;

    float acc[4][8][4];
#pragma unroll
    for (int mf = 0; mf < 4; mf++)
#pragma unroll
        for (int nf = 0; nf < 8; nf++)
#pragma unroll
            for (int i = 0; i < 4; i++) acc[mf][nf][i] = 0.f;

    // loader: per stage, A: 128 rows x 4 chunks(16B) = 512 ops, B: 384 x 4 = 1536 ops
    // prologue: stages 0..NS-2
#pragma unroll
    for (int s = 0; s < NS - 1; s++) {
        __half* As = smem + s * STGH;
        __half* Bs = As + BM * SKH;
        const int k0 = s * BK;
        {
            int c = tid;                   // A: 512 ops, threads 384 -> 2 iters (2nd partial)
            int row = c >> 2, col = (c & 3) * 8;
            cp16(As + row * SKH + col, asrc0 + (size_t)row * D_ + k0 + col);
            c = tid + 384;
            if (c < 512) {
                row = c >> 2; col = (c & 3) * 8;
                cp16(As + row * SKH + col, asrc0 + (size_t)row * D_ + k0 + col);
            }
        }
#pragma unroll
        for (int i = 0; i < 4; i++) {      // B: 1536 ops
            int c = tid + 384 * i;
            int row = c >> 2, col = (c & 3) * 8;
            cp16(Bs + row * SKH + col, bsrc0 + (size_t)row * D_ + k0 + col);
        }
        cp_commit();
    }

    for (int kt = 0; kt < KT; kt++) {
        cp_wait<NS - 2>();
        __syncthreads();

        // refill stage freed by last iteration's compute, BEFORE this compute
        const int kn = kt + NS - 1;
        if (kn < KT) {
            __half* Asw = smem + (kn % NS) * STGH;
            __half* Bsw = Asw + BM * SKH;
            const int k0 = kn * BK;
            {
                int c = tid;
                int row = c >> 2, col = (c & 3) * 8;
                cp16(Asw + row * SKH + col, asrc0 + (size_t)row * D_ + k0 + col);
                c = tid + 384;
                if (c < 512) {
                    row = c >> 2; col = (c & 3) * 8;
                    cp16(Asw + row * SKH + col, asrc0 + (size_t)row * D_ + k0 + col);
                }
            }
#pragma unroll
            for (int i = 0; i < 4; i++) {
                int c = tid + 384 * i;
                int row = c >> 2, col = (c & 3) * 8;
                cp16(Bsw + row * SKH + col, bsrc0 + (size_t)row * D_ + k0 + col);
            }
        }
        cp_commit();

        const __half* As = smem + (kt % NS) * STGH;
        const __half* Bs = As + BM * SKH;

#pragma unroll
        for (int kk = 0; kk < BK; kk += 16) {
            uint32_t af[4][4], bf[8][2];
#pragma unroll
            for (int mf = 0; mf < 4; mf++) {
                const uint2 v0 = *(const uint2*)(As + (wm + mf * 16 + g) * SKH + kk + 4 * t4);
                const uint2 v1 = *(const uint2*)(As + (wm + mf * 16 + g + 8) * SKH + kk + 4 * t4);
                af[mf][0] = v0.x;
                af[mf][1] = v1.x;
                af[mf][2] = v0.y;
                af[mf][3] = v1.y;
            }
#pragma unroll
            for (int nf = 0; nf < 8; nf++) {
                const uint2 v = *(const uint2*)(Bs + (wn + nf * 8 + g) * SKH + kk + 4 * t4);
                bf[nf][0] = v.x;
                bf[nf][1] = v.y;
            }
#pragma unroll
            for (int mf = 0; mf < 4; mf++)
#pragma unroll
                for (int nf = 0; nf < 8; nf++)
                    mma_f16(acc[mf][nf], af[mf], bf[nf]);
        }
    }

    // ---------------- epilogue ----------------
    const int gcol0  = nt * BN + wn;       // warp's first global column (64-aligned)
    const int region = gcol0 >> 10;        // 0: s, 1: y1, 2: y2

    if (nt * BN < 1024) {                  // CTA contains region-0 warps
        __syncthreads();
        float* s_sm = (float*)smem;
        if (tid < BM) s_sm[tid] = 0.f;
        __syncthreads();
        if (region == 0) {
#pragma unroll
            for (int mf = 0; mf < 4; mf++) {
                float lo = 0.f, hi = 0.f;
#pragma unroll
                for (int nf = 0; nf < 8; nf++) {
                    int col = gcol0 + nf * 8 + 2 * t4;
                    float bb0 = __ldg(b1 + col), bb1 = __ldg(b1 + col + 1);
                    float ww0 = __ldg(w2 + col), ww1 = __ldg(w2 + col + 1);
                    lo += tanhf(acc[mf][nf][0] + bb0) * ww0 + tanhf(acc[mf][nf][1] + bb1) * ww1;
                    hi += tanhf(acc[mf][nf][2] + bb0) * ww0 + tanhf(acc[mf][nf][3] + bb1) * ww1;
                }
                lo += __shfl_xor_sync(0xffffffffu, lo, 1);
                lo += __shfl_xor_sync(0xffffffffu, lo, 2);
                hi += __shfl_xor_sync(0xffffffffu, hi, 1);
                hi += __shfl_xor_sync(0xffffffffu, hi, 2);
                if (t4 == 0) {
                    atomicAdd(&s_sm[wm + mf * 16 + g], lo);
                    atomicAdd(&s_sm[wm + mf * 16 + g + 8], hi);
                }
            }
        }
        __syncthreads();
        if (tid < BM) atomicAdd(&g_s[m0 + tid], s_sm[tid]);
    }
    if (region != 0) {
        float* y = (region == 1) ? g_y1 : g_y2;
        const int c0 = gcol0 - region * 1024;
#pragma unroll
        for (int mf = 0; mf < 4; mf++) {
            int row = m0 + wm + mf * 16 + g;
#pragma unroll
            for (int nf = 0; nf < 8; nf++) {
                int col = c0 + nf * 8 + 2 * t4;
                *(float2*)(y + (size_t)row * D_ + col)       = make_float2(acc[mf][nf][0], acc[mf][nf][1]);
                *(float2*)(y + (size_t)(row + 8) * D_ + col) = make_float2(acc[mf][nf][2], acc[mf][nf][3]);
            }
        }
    }
}

// ---------------- scalar pipeline ----------------
__global__ void k_init_s(const float* __restrict__ b2) {
    int i = blockIdx.x * blockDim.x + threadIdx.x;
    if (i < BT_) g_s[i] = b2[0];
}

__global__ void k_maxexp() {
    __shared__ float red[256];
    const int b = blockIdx.x;
    const float* s = g_s + b * T_;
    float m = -1e30f;
    for (int i = threadIdx.x; i < T_; i += 256) m = fmaxf(m, s[i]);
    red[threadIdx.x] = m;
    __syncthreads();
    for (int st = 128; st > 0; st >>= 1) {
        if (threadIdx.x < st) red[threadIdx.x] = fmaxf(red[threadIdx.x], red[threadIdx.x + st]);
        __syncthreads();
    }
    m = red[0];
    for (int i = threadIdx.x; i < T_; i += 256) g_e[b * T_ + i] = expf(s[i] - m);
}

__global__ void k_partial() {
    __shared__ float e_sh[TT];
    const int tile = blockIdx.x, b = blockIdx.y, tid = threadIdx.x;
    const int t0 = tile * TT;
    if (tid < TT) e_sh[tid] = g_e[b * T_ + t0 + tid];
    __syncthreads();
    const int d0 = tid * 4;
    const float4* yp = (const float4*)(g_y1 + (size_t)(b * T_ + t0) * D_ + d0);
    float4 acc = make_float4(0.f, 0.f, 0.f, 0.f);
#pragma unroll 4
    for (int t = 0; t < TT; t++) {
        float4 yv = yp[t * (D_ / 4)];
        float e = e_sh[t];
        acc.x += e * yv.x; acc.y += e * yv.y; acc.z += e * yv.z; acc.w += e * yv.w;
    }
    *(float4*)(g_pex + (size_t)(b * NTILE + tile) * D_ + d0) = acc;
    if (tid == 0) {
        float se = 0.f;
        for (int t = 0; t < TT; t++) se += e_sh[t];
        g_pe[b * NTILE + tile] = se;
    }
}

// exclusive scan across tiles; grid (B_, 4), one d-column per thread (coalesced)
__global__ void k_scan() {
    const int b = blockIdx.x;
    const int d = blockIdx.y * 256 + threadIdx.x;
    float run = 0.f;
#pragma unroll 8
    for (int tile = 0; tile < NTILE; tile++) {
        float* p = g_pex + (size_t)(b * NTILE + tile) * D_ + d;
        float v = *p;
        *p = run;
        run += v;
    }
    if (blockIdx.y == 0 && threadIdx.x == 0) {
        float r = 0.f;
        for (int tile = 0; tile < NTILE; tile++) {
            float v = g_pe[b * NTILE + tile];
            g_pe[b * NTILE + tile] = r;
            r += v;
        }
    }
}

__global__ void k_final(const float* __restrict__ bc, float* __restrict__ out) {
    __shared__ float e_sh[TT], den_sh[TT];
    const int tile = blockIdx.x, b = blockIdx.y, tid = threadIdx.x;
    const int t0 = tile * TT;
    if (tid < TT) e_sh[tid] = g_e[b * T_ + t0 + tid];
    __syncthreads();
    if (tid == 0) {
        float r = g_pe[b * NTILE + tile];
        for (int t = 0; t < TT; t++) { r += e_sh[t]; den_sh[t] = r; }
    }
    __syncthreads();
    const int d0 = tid * 4;
    float4 run = *(float4*)(g_pex + (size_t)(b * NTILE + tile) * D_ + d0);
    float4 bcv = *(const float4*)(bc + d0);
    const float4* y1p = (const float4*)(g_y1 + (size_t)(b * T_ + t0) * D_ + d0);
    const float4* y2p = (const float4*)(g_y2 + (size_t)(b * T_ + t0) * D_ + d0);
    float4* op = (float4*)(out + (size_t)(b * T_ + t0) * D_ + d0);
#pragma unroll 4
    for (int t = 0; t < TT; t++) {
        float4 y1v = y1p[t * (D_ / 4)];
        float4 y2v = y2p[t * (D_ / 4)];
        float e = e_sh[t];
        run.x += e * y1v.x; run.y += e * y1v.y; run.z += e * y1v.z; run.w += e * y1v.w;
        float inv = 1.0f / den_sh[t];
        float4 o;
        o.x = tanhf(run.x * inv + y2v.x + bcv.x);
        o.y = tanhf(run.y * inv + y2v.y + bcv.y);
        o.z = tanhf(run.z * inv + y2v.z + bcv.z);
        o.w = tanhf(run.w * inv + y2v.w + bcv.w);
        op[t * (D_ / 4)] = o;
    }
}

// ---------------- launch ----------------
extern "C" void kernel_launch(void* const* d_in, const int* in_sizes, int n_in,
                              void* d_out, int out_size)
{
    const float* x  = (const float*)d_in[0];
    const float* W1 = (const float*)d_in[1];
    const float* b1 = (const float*)d_in[2];
    const float* w2 = (const float*)d_in[3];
    const float* b2 = (const float*)d_in[4];
    const float* Wc = (const float*)d_in[5];
    const float* bc = (const float*)d_in[6];
    float* out = (float*)d_out;

    cudaFuncSetAttribute(gemm_big, cudaFuncAttributeMaxDynamicSharedMemorySize, SMEM_BYTES);

    k_pack_x<<<(BT_ * (D_ / 16)) / 256, 256>>>(x);
    k_pack_w<<<(NBIG * (D_ / 16)) / 256, 256>>>(W1, Wc);
    k_init_s<<<BT_ / 256, 256>>>(b2);

    dim3 gg(NBIG / BN, BT_ / BM);   // (8, 256)
    gemm_big<<<gg, NTH, SMEM_BYTES>>>(b1, w2);

    k_maxexp<<<B_, 256>>>();

    dim3 gp(NTILE, B_);
    k_partial<<<gp, 256>>>();
    dim3 gs(B_, 4);
    k_scan<<<gs, 256>>>();
    k_final<<<gp, 256>>>(bc, out);
}